// round 15
// baseline (speedup 1.0000x reference)
#include <cuda_runtime.h>
#include <cuda_bf16.h>
#include <math_constants.h>
#include <cstdint>

#define NQ        256
#define NK        50000
#define DD        64
#define KT        128
#define NKT       391          // ceil(50000/128)
#define NKPAD     (NKT * KT)   // 50048
#define GRIDC     148          // persistent CTA columns for score kernel
#define GRP       16           // candidate granularity (keys per group)
#define NHG       (NKT * 8)    // 3128 groups
#define OBS_ELEMS 3072
#define CAP       128
#define MARGIN    1.0f         // >> 2x single-bf16 score error bound

// ---- static device scratch ----
__device__ __align__(16) __nv_bfloat16 g_kbf[NKPAD * DD];  // pre-converted k
__device__ __align__(16) float g_ksq[NKPAD];               // ||k||^2 (INF pad)
__device__ __align__(16) float g_hmin[NQ * NHG];
__device__ int   g_topidx[NQ * 8];

// ---- score-kernel smem (bytes) ----
#define TSTRIDE_B  144
#define SM_Q     0             // 128 x 144 bf16 rows = 18432
#define SM_K0    18432         // 128 x 144           = 18432
#define SM_K1    36864         //                     = 18432
#define SM_KSQ0  55296         // 128 f32             = 512
#define SM_KSQ1  55808         //                     = 512
#define SM_HST   56320         // 128 x 8 f32         = 4096
#define SM_TOTAL 60416

// ============================ helpers ============================
__device__ __forceinline__ uint32_t smem_u32(const void* p) {
    uint32_t a;
    asm("{ .reg .u64 t; cvta.to.shared.u64 t, %1; cvt.u32.u64 %0, t; }" : "=r"(a) : "l"(p));
    return a;
}
__device__ __forceinline__ void ldsm_x4(uint32_t& r0, uint32_t& r1, uint32_t& r2,
                                        uint32_t& r3, uint32_t a) {
    asm volatile("ldmatrix.sync.aligned.m8n8.x4.shared.b16 {%0,%1,%2,%3}, [%4];"
                 : "=r"(r0), "=r"(r1), "=r"(r2), "=r"(r3) : "r"(a));
}
__device__ __forceinline__ void mma_bf16(float& c0, float& c1, float& c2, float& c3,
                                         uint32_t a0, uint32_t a1, uint32_t a2, uint32_t a3,
                                         uint32_t b0, uint32_t b1) {
    asm volatile("mma.sync.aligned.m16n8k16.row.col.f32.bf16.bf16.f32 "
                 "{%0,%1,%2,%3},{%4,%5,%6,%7},{%8,%9},{%0,%1,%2,%3};"
                 : "+f"(c0), "+f"(c1), "+f"(c2), "+f"(c3)
                 : "r"(a0), "r"(a1), "r"(a2), "r"(a3), "r"(b0), "r"(b1));
}
__device__ __forceinline__ void cp_async16(uint32_t dst, const void* src) {
    asm volatile("cp.async.cg.shared.global [%0], [%1], 16;" :: "r"(dst), "l"(src));
}

// convert 32 floats -> bf16 row chunk in smem
__device__ __forceinline__ void cvt_row_bf16(char* dst, const float4* __restrict__ s) {
    uint2* d = (uint2*)dst;
    #pragma unroll
    for (int i = 0; i < 8; i++) {
        float4 v = s[i];
        __nv_bfloat162 p0 = __floats2bfloat162_rn(v.x, v.y);
        __nv_bfloat162 p1 = __floats2bfloat162_rn(v.z, v.w);
        uint2 u;
        u.x = *(uint32_t*)&p0;
        u.y = *(uint32_t*)&p1;
        d[i] = u;
    }
}

// ======================================================================
// Kernel 0: one-time k fp32 -> bf16 (flat 128 B rows) + ksq, padded.
// grid 196 x 256 threads; one row per thread.
// ======================================================================
__global__ __launch_bounds__(256) void knn_prep(const float* __restrict__ km)
{
    const int row = blockIdx.x * 256 + threadIdx.x;
    if (row >= NKPAD) return;
    uint4* dst = (uint4*)(g_kbf + (size_t)row * DD);
    if (row < NK) {
        const float4* s = (const float4*)(km + (size_t)row * DD);
        float ss = 0.f;
        #pragma unroll
        for (int i = 0; i < 8; i++) {
            float4 v0 = s[i * 2], v1 = s[i * 2 + 1];
            ss = fmaf(v0.x, v0.x, ss); ss = fmaf(v0.y, v0.y, ss);
            ss = fmaf(v0.z, v0.z, ss); ss = fmaf(v0.w, v0.w, ss);
            ss = fmaf(v1.x, v1.x, ss); ss = fmaf(v1.y, v1.y, ss);
            ss = fmaf(v1.z, v1.z, ss); ss = fmaf(v1.w, v1.w, ss);
            __nv_bfloat162 a = __floats2bfloat162_rn(v0.x, v0.y);
            __nv_bfloat162 b = __floats2bfloat162_rn(v0.z, v0.w);
            __nv_bfloat162 c = __floats2bfloat162_rn(v1.x, v1.y);
            __nv_bfloat162 d = __floats2bfloat162_rn(v1.z, v1.w);
            uint4 u;
            u.x = *(uint32_t*)&a; u.y = *(uint32_t*)&b;
            u.z = *(uint32_t*)&c; u.w = *(uint32_t*)&d;
            dst[i] = u;
        }
        g_ksq[row] = ss;
    } else {
        uint4 z = make_uint4(0u, 0u, 0u, 0u);
        #pragma unroll
        for (int i = 0; i < 8; i++) dst[i] = z;
        g_ksq[row] = CUDART_INF_F;
    }
}

// ======================================================================
// Kernel 1: persistent pipelined bf16 GEMM -> per-(query,16-key-group) MIN
// grid (148, 2), 256 threads (8 warps: 4 m-rows x 2 n-cols)
// Each CTA: 128 queries (half) x tiles c, c+148, c+296. 2 CTAs/SM.
// ======================================================================
__device__ __forceinline__ void load_ktile_async(uint32_t sb, int t, int buf, int tid) {
    const uint32_t kdst = sb + (buf ? SM_K1 : SM_K0);
    // 1024 16B chunks, 4 per thread
    #pragma unroll
    for (int i = 0; i < 4; i++) {
        const int cid = tid + i * 256;
        const int row = cid >> 3, part = cid & 7;
        const char* src = (const char*)g_kbf + ((size_t)(t * KT + row) * DD + part * 8) * 2;
        cp_async16(kdst + row * TSTRIDE_B + part * 16, src);
    }
    if (tid < 32)
        cp_async16(sb + (buf ? SM_KSQ1 : SM_KSQ0) + tid * 16,
                   (const char*)g_ksq + (size_t)(t * KT + tid * 4) * 4);
}

__global__ __launch_bounds__(256, 2) void knn_score_min(
    const float* __restrict__ qm)
{
    extern __shared__ char smem[];
    const uint32_t sb = smem_u32(smem);
    const int tid  = threadIdx.x;
    const int wid  = tid >> 5;
    const int lane = tid & 31;
    const int c    = blockIdx.x;
    const int qh   = blockIdx.y;        // query half 0/1
    const int q0   = qh * 128;
    const int n_it = (c < NKT - 2 * GRIDC) ? 3 : 2;   // 95 cols do 3, rest 2

    float* stage = (float*)(smem + SM_HST);

    // ---- prologue: convert this half's q tile; async-load k tile c ----
    load_ktile_async(sb, c, 0, tid);
    asm volatile("cp.async.commit_group;" ::: "memory");
    {
        const int row = tid >> 1, hf = tid & 1;
        cvt_row_bf16(smem + SM_Q + row * TSTRIDE_B + hf * 64,
                     (const float4*)(qm + (size_t)(q0 + row) * DD + hf * 32));
    }
    asm volatile("cp.async.wait_group 0;" ::: "memory");
    __syncthreads();

    const int mrow = wid >> 1;          // 0..3
    const int ncol = wid & 1;           // 0..1
    int p = 0;

    for (int it = 0; it < n_it; it++) {
        const int t = c + it * GRIDC;
        const bool have_next = (it + 1 < n_it);

        // ---- prefetch next bf16 k tile (no conversion needed) ----
        if (have_next) {
            load_ktile_async(sb, t + GRIDC, 1 - p, tid);
            asm volatile("cp.async.commit_group;" ::: "memory");
        }

        // ---- GEMM from buffer p ----
        const uint32_t kbase = sb + (p ? SM_K1 : SM_K0);
        const float* ksq = (const float*)(smem + (p ? SM_KSQ1 : SM_KSQ0));

        float acc[2][8][4];
        #pragma unroll
        for (int mt = 0; mt < 2; mt++)
            #pragma unroll
            for (int nt = 0; nt < 8; nt++)
                #pragma unroll
                for (int cc = 0; cc < 4; cc++) acc[mt][nt][cc] = 0.f;

        #pragma unroll
        for (int ks16 = 0; ks16 < 4; ks16++) {
            const uint32_t dby = ks16 * 32;
            uint32_t a[2][4];
            #pragma unroll
            for (int mt = 0; mt < 2; mt++) {
                uint32_t addr = sb + SM_Q
                    + (uint32_t)(mrow * 32 + mt * 16 + (lane & 15)) * TSTRIDE_B
                    + dby + ((lane >> 4) << 4);
                ldsm_x4(a[mt][0], a[mt][1], a[mt][2], a[mt][3], addr);
            }
            uint32_t b[8][2];
            #pragma unroll
            for (int np = 0; np < 4; np++) {
                uint32_t n = (uint32_t)(ncol * 64 + np * 16 + ((lane >> 4) << 3) + (lane & 7));
                uint32_t addr = kbase + n * TSTRIDE_B + dby + (((lane >> 3) & 1) << 4);
                ldsm_x4(b[np * 2][0], b[np * 2][1], b[np * 2 + 1][0], b[np * 2 + 1][1], addr);
            }
            #pragma unroll
            for (int mt = 0; mt < 2; mt++)
                #pragma unroll
                for (int nt = 0; nt < 8; nt++)
                    mma_bf16(acc[mt][nt][0], acc[mt][nt][1], acc[mt][nt][2], acc[mt][nt][3],
                             a[mt][0], a[mt][1], a[mt][2], a[mt][3],
                             b[nt][0], b[nt][1]);
        }

        // ---- epilogue: per-(row, 16-col-group) min -> smem stage ----
        {
            const int g = lane >> 2, tq = lane & 3;
            #pragma unroll
            for (int mt = 0; mt < 2; mt++) {
                const int rowb = mrow * 32 + mt * 16 + g;
                #pragma unroll
                for (int gi = 0; gi < 4; gi++) {
                    float m0 = CUDART_INF_F, m1 = CUDART_INF_F;
                    #pragma unroll
                    for (int e = 0; e < 2; e++) {
                        const int nt = gi * 2 + e;
                        const int col = ncol * 64 + nt * 8 + tq * 2;
                        const float kq0 = ksq[col], kq1 = ksq[col + 1];
                        m0 = fminf(m0, fminf(fmaf(-2.f, acc[mt][nt][0], kq0),
                                             fmaf(-2.f, acc[mt][nt][1], kq1)));
                        m1 = fminf(m1, fminf(fmaf(-2.f, acc[mt][nt][2], kq0),
                                             fmaf(-2.f, acc[mt][nt][3], kq1)));
                    }
                    m0 = fminf(m0, __shfl_xor_sync(0xFFFFFFFFu, m0, 1));
                    m0 = fminf(m0, __shfl_xor_sync(0xFFFFFFFFu, m0, 2));
                    m1 = fminf(m1, __shfl_xor_sync(0xFFFFFFFFu, m1, 1));
                    m1 = fminf(m1, __shfl_xor_sync(0xFFFFFFFFu, m1, 2));
                    if (tq == 0) {
                        const int gg = ncol * 4 + gi;
                        stage[rowb * 8 + gg]       = m0;
                        stage[(rowb + 8) * 8 + gg] = m1;
                    }
                }
            }
        }
        __syncthreads();

        // ---- coalesced write-out of this tile's group mins ----
        {
            const int row = tid >> 1, half = tid & 1;
            float4 v = *(float4*)&stage[row * 8 + half * 4];
            *(float4*)&g_hmin[(size_t)(q0 + row) * NHG + t * 8 + half * 4] = v;
        }

        if (have_next) {
            asm volatile("cp.async.wait_group 0;" ::: "memory");
        }
        __syncthreads();
        p ^= 1;
    }
}

// ======================================================================
// Kernel 2: (byte-identical to round-10/14) cutoff -> compact -> exact
//           fp32 rescore -> exact top-8. grid NQ, 256 threads.
// ======================================================================
#define INS8T(s_, j_)                                                            \
    if ((s_) < l[7] || ((s_) == l[7] && (j_) < li[7])) {                         \
        l[7] = (s_); li[7] = (j_);                                               \
        _Pragma("unroll")                                                        \
        for (int u = 7; u > 0; u--)                                              \
            if (l[u] < l[u-1] || (l[u] == l[u-1] && li[u] < li[u-1])) {          \
                float ts = l[u]; l[u] = l[u-1]; l[u-1] = ts;                     \
                int ti = li[u]; li[u] = li[u-1]; li[u-1] = ti; }                 \
    }

#define INS1(s_)                                                                 \
    if ((s_) < l[7]) {                                                           \
        l[7] = (s_);                                                             \
        _Pragma("unroll")                                                        \
        for (int u = 7; u > 0; u--)                                              \
            if (l[u] < l[u-1]) { float ts = l[u]; l[u] = l[u-1]; l[u-1] = ts; }  \
    }

__global__ __launch_bounds__(256) void knn_select(
    const float* __restrict__ qm, const float* __restrict__ km)
{
    __shared__ float qs[64];
    __shared__ float ms[256 * 8];
    __shared__ int   mi[256 * 8];
    __shared__ int   s_list[CAP];
    __shared__ int   s_cnt;
    __shared__ float s_cut;
    const int q = blockIdx.x, tid = threadIdx.x;

    if (tid < 64) qs[tid] = qm[(size_t)q * DD + tid];
    if (tid == 0) s_cnt = 0;

    const float4* h4 = (const float4*)&g_hmin[(size_t)q * NHG];
    const int NV = NHG / 4;   // 782 float4

    // ---- phase A: per-thread top-8 of group-mins (float4 loads) ----
    float l[8];
    #pragma unroll
    for (int i = 0; i < 8; i++) l[i] = CUDART_INF_F;
    #pragma unroll
    for (int r = 0; r < 4; r++) {
        const int v4 = tid + r * 256;
        if (v4 < NV) {
            float4 v = h4[v4];
            INS1(v.x); INS1(v.y); INS1(v.z); INS1(v.w);
        }
    }
    #pragma unroll
    for (int m = 0; m < 8; m++) ms[tid * 8 + m] = l[m];

    for (int st = 128; st >= 1; st >>= 1) {
        __syncthreads();
        if (tid < st) {
            const int o = (tid + st) * 8;
            #pragma unroll 1
            for (int m = 0; m < 8; m++) {
                float s = ms[o + m];
                if (s >= l[7]) break;
                INS1(s);
            }
            #pragma unroll
            for (int m = 0; m < 8; m++) ms[tid * 8 + m] = l[m];
        }
    }
    if (tid == 0) s_cut = l[7] + MARGIN;
    __syncthreads();

    // ---- phase B: compact candidate 16-key groups (float4 loads) ----
    const float cut = s_cut;
    #pragma unroll
    for (int r = 0; r < 4; r++) {
        const int v4 = tid + r * 256;
        if (v4 < NV) {
            float4 v = h4[v4];
            if (v.x <= cut) { int p = atomicAdd(&s_cnt, 1); if (p < CAP) s_list[p] = v4 * 4; }
            if (v.y <= cut) { int p = atomicAdd(&s_cnt, 1); if (p < CAP) s_list[p] = v4 * 4 + 1; }
            if (v.z <= cut) { int p = atomicAdd(&s_cnt, 1); if (p < CAP) s_list[p] = v4 * 4 + 2; }
            if (v.w <= cut) { int p = atomicAdd(&s_cnt, 1); if (p < CAP) s_list[p] = v4 * 4 + 3; }
        }
    }
    __syncthreads();
    const int cnt = (s_cnt < CAP) ? s_cnt : CAP;

    // ---- phase C: exact fp32 rescore of cnt*16 keys ----
    int li[8];
    #pragma unroll
    for (int i = 0; i < 8; i++) { l[i] = CUDART_INF_F; li[i] = 0x7FFFFFFF; }

    const float4* qp = (const float4*)qs;
    for (int u = tid; u < cnt * GRP; u += 256) {
        const int j = s_list[u >> 4] * GRP + (u & 15);
        if (j < NK) {
            const float4* kp = (const float4*)(km + (size_t)j * DD);
            float dot = 0.f, ks = 0.f;
            #pragma unroll
            for (int w = 0; w < 16; w++) {
                float4 kv = kp[w];
                float4 qv = qp[w];
                dot = fmaf(kv.x, qv.x, dot); ks = fmaf(kv.x, kv.x, ks);
                dot = fmaf(kv.y, qv.y, dot); ks = fmaf(kv.y, kv.y, ks);
                dot = fmaf(kv.z, qv.z, dot); ks = fmaf(kv.z, kv.z, ks);
                dot = fmaf(kv.w, qv.w, dot); ks = fmaf(kv.w, kv.w, ks);
            }
            float s = fmaf(-2.f, dot, ks);
            INS8T(s, j);
        }
    }
    #pragma unroll
    for (int m = 0; m < 8; m++) { ms[tid * 8 + m] = l[m]; mi[tid * 8 + m] = li[m]; }

    for (int st = 128; st >= 1; st >>= 1) {
        __syncthreads();
        if (tid < st) {
            const int o = (tid + st) * 8;
            #pragma unroll 1
            for (int m = 0; m < 8; m++) {
                float s = ms[o + m];
                int   j = mi[o + m];
                bool better = (s < l[7]) || (s == l[7] && j < li[7]);
                if (!better) break;
                l[7] = s; li[7] = j;
                #pragma unroll
                for (int u = 7; u > 0; u--)
                    if (l[u] < l[u-1] || (l[u] == l[u-1] && li[u] < li[u-1])) {
                        float ts = l[u]; l[u] = l[u-1]; l[u-1] = ts;
                        int ti = li[u]; li[u] = li[u-1]; li[u-1] = ti;
                    }
            }
            #pragma unroll
            for (int m = 0; m < 8; m++) { ms[tid * 8 + m] = l[m]; mi[tid * 8 + m] = li[m]; }
        }
    }
    if (tid == 0) {
        #pragma unroll
        for (int m = 0; m < 8; m++) g_topidx[q * 8 + m] = li[m];
    }
}

// ======================================================================
// Kernel 3: gather obs[idx] -> out [8, 256, 3072]  (2048 blocks, max MLP)
// ======================================================================
__global__ __launch_bounds__(256) void knn_gather_kernel(
    const float* __restrict__ obs, float* __restrict__ out)
{
    const int b  = blockIdx.x;
    const int kk = b >> 8;
    const int q  = b & 255;
    const int src = g_topidx[q * 8 + kk];

    const float4* s = (const float4*)(obs + (size_t)src * OBS_ELEMS);
    float4*       d = (float4*)(out + ((size_t)kk * NQ + q) * OBS_ELEMS);

    #pragma unroll
    for (int i = threadIdx.x; i < OBS_ELEMS / 4; i += 256)
        d[i] = s[i];
}

// ======================================================================
extern "C" void kernel_launch(void* const* d_in, const int* in_sizes, int n_in,
                              void* d_out, int out_size)
{
    const float* q   = (const float*)d_in[0];
    const float* k   = (const float*)d_in[1];
    const float* obs = (const float*)d_in[2];
    float* out = (float*)d_out;

    cudaFuncSetAttribute(knn_score_min,
                         cudaFuncAttributeMaxDynamicSharedMemorySize, SM_TOTAL);

    knn_prep<<<(NKPAD + 255) / 256, 256>>>(k);
    knn_score_min<<<dim3(GRIDC, 2), 256, SM_TOTAL>>>(q);
    knn_select<<<NQ, 256>>>(q, k);
    knn_gather_kernel<<<NQ * 8, 256>>>(obs, out);
}

// round 16
// speedup vs baseline: 1.4826x; 1.4826x over previous
#include <cuda_runtime.h>
#include <cuda_bf16.h>
#include <math_constants.h>
#include <cstdint>

#define NQ        256
#define NK        50000
#define DD        64
#define KT        128
#define NKT       391          // ceil(50000/128)
#define GRID1     148          // persistent CTAs for score kernel
#define GRP       16           // candidate granularity (keys per group)
#define NHG       (NKT * 8)    // 3128 groups
#define OBS_ELEMS 3072
#define CAP       128
#define MARGIN    1.0f         // >> 2x single-bf16 score error bound

// ---- static device scratch ----
__device__ __align__(16) float g_hmin[NQ * NHG];
__device__ int   g_topidx[NQ * 8];

// ---- kernel-1 smem (bytes) ----
#define TSTRIDE_B  144
#define SM_Q     0             // 256 x 144 bf16 rows      = 36864
#define SM_K0    36864         // 128 x 144                = 18432
#define SM_K1    55296         //                          = 18432
#define SM_KSQ0  73728         // 128 f32                  = 512
#define SM_KSQ1  74240         //                          = 512
#define SM_ST32  74752         // fp32 k staging 128x256B  = 32768
#define SM_HST   107520        // hmin stage 256x8 f32     = 8192
#define SM_TOTAL 115712

// ============================ helpers ============================
__device__ __forceinline__ uint32_t smem_u32(const void* p) {
    uint32_t a;
    asm("{ .reg .u64 t; cvta.to.shared.u64 t, %1; cvt.u32.u64 %0, t; }" : "=r"(a) : "l"(p));
    return a;
}
__device__ __forceinline__ void ldsm_x4(uint32_t& r0, uint32_t& r1, uint32_t& r2,
                                        uint32_t& r3, uint32_t a) {
    asm volatile("ldmatrix.sync.aligned.m8n8.x4.shared.b16 {%0,%1,%2,%3}, [%4];"
                 : "=r"(r0), "=r"(r1), "=r"(r2), "=r"(r3) : "r"(a));
}
__device__ __forceinline__ void mma_bf16(float& c0, float& c1, float& c2, float& c3,
                                         uint32_t a0, uint32_t a1, uint32_t a2, uint32_t a3,
                                         uint32_t b0, uint32_t b1) {
    asm volatile("mma.sync.aligned.m16n8k16.row.col.f32.bf16.bf16.f32 "
                 "{%0,%1,%2,%3},{%4,%5,%6,%7},{%8,%9},{%0,%1,%2,%3};"
                 : "+f"(c0), "+f"(c1), "+f"(c2), "+f"(c3)
                 : "r"(a0), "r"(a1), "r"(a2), "r"(a3), "r"(b0), "r"(b1));
}
__device__ __forceinline__ void cp_async16(uint32_t dst, const void* src) {
    asm volatile("cp.async.cg.shared.global [%0], [%1], 16;" :: "r"(dst), "l"(src));
}

// convert 32 floats -> bf16 row chunk in smem, accumulate sum of squares
__device__ __forceinline__ void cvt_row_bf16(char* dst, const float4* __restrict__ s,
                                             float& ss) {
    uint2* d = (uint2*)dst;
    #pragma unroll
    for (int i = 0; i < 8; i++) {
        float4 v = s[i];
        ss = fmaf(v.x, v.x, ss); ss = fmaf(v.y, v.y, ss);
        ss = fmaf(v.z, v.z, ss); ss = fmaf(v.w, v.w, ss);
        __nv_bfloat162 p0 = __floats2bfloat162_rn(v.x, v.y);
        __nv_bfloat162 p1 = __floats2bfloat162_rn(v.z, v.w);
        uint2 u;
        u.x = *(uint32_t*)&p0;
        u.y = *(uint32_t*)&p1;
        d[i] = u;
    }
}

// ======================================================================
// Kernel 1: persistent pipelined bf16 GEMM -> per-(query,16-key-group) MIN
// (byte-identical to round-14) grid 148, 512 threads
// ======================================================================
__global__ __launch_bounds__(512, 1) void knn_score_min(
    const float* __restrict__ qm, const float* __restrict__ km)
{
    extern __shared__ char smem[];
    const uint32_t sb = smem_u32(smem);
    const int tid  = threadIdx.x;
    const int wid  = tid >> 5;
    const int lane = tid & 31;
    const int c    = blockIdx.x;
    const int n_it = (c < NKT - 2 * GRID1) ? 3 : 2;

    float* stage = (float*)(smem + SM_HST);

    {
        const int row = tid >> 1, hf = tid & 1;
        float dummy = 0.f;
        cvt_row_bf16(smem + SM_Q + row * TSTRIDE_B + hf * 64,
                     (const float4*)(qm + (size_t)row * DD + hf * 32), dummy);
        if (tid < 256) {
            const int j = c * KT + row;
            float ss = 0.f;
            cvt_row_bf16(smem + SM_K0 + row * TSTRIDE_B + hf * 64,
                         (const float4*)(km + (size_t)j * DD + hf * 32), ss);
            float tot = ss + __shfl_xor_sync(0xFFFFFFFFu, ss, 1);
            if (hf == 0) ((float*)(smem + SM_KSQ0))[row] = tot;
        }
    }
    __syncthreads();

    const int mrow = wid >> 1;
    const int ncol = wid & 1;
    int p = 0;

    for (int it = 0; it < n_it; it++) {
        const int t = c + it * GRID1;
        const bool have_next = (it + 1 < n_it);

        if (have_next) {
            const int tn = t + GRID1;
            const int row = tid >> 2, qtr = tid & 3;
            int j = tn * KT + row;
            if (j >= NK) j = NK - 1;
            const char* src = (const char*)(km + (size_t)j * DD) + qtr * 64;
            uint32_t dst = sb + SM_ST32 + row * 256 + qtr * 64;
            #pragma unroll
            for (int i = 0; i < 4; i++)
                cp_async16(dst + i * 16, src + i * 16);
            asm volatile("cp.async.commit_group;" ::: "memory");
        }

        const uint32_t kbase = sb + (p ? SM_K1 : SM_K0);
        const float* ksq = (const float*)(smem + (p ? SM_KSQ1 : SM_KSQ0));

        float acc[2][8][4];
        #pragma unroll
        for (int mt = 0; mt < 2; mt++)
            #pragma unroll
            for (int nt = 0; nt < 8; nt++)
                #pragma unroll
                for (int cc = 0; cc < 4; cc++) acc[mt][nt][cc] = 0.f;

        #pragma unroll
        for (int ks16 = 0; ks16 < 4; ks16++) {
            const uint32_t dby = ks16 * 32;
            uint32_t a[2][4];
            #pragma unroll
            for (int mt = 0; mt < 2; mt++) {
                uint32_t addr = sb + SM_Q
                    + (uint32_t)(mrow * 32 + mt * 16 + (lane & 15)) * TSTRIDE_B
                    + dby + ((lane >> 4) << 4);
                ldsm_x4(a[mt][0], a[mt][1], a[mt][2], a[mt][3], addr);
            }
            uint32_t b[8][2];
            #pragma unroll
            for (int np = 0; np < 4; np++) {
                uint32_t n = (uint32_t)(ncol * 64 + np * 16 + ((lane >> 4) << 3) + (lane & 7));
                uint32_t addr = kbase + n * TSTRIDE_B + dby + (((lane >> 3) & 1) << 4);
                ldsm_x4(b[np * 2][0], b[np * 2][1], b[np * 2 + 1][0], b[np * 2 + 1][1], addr);
            }
            #pragma unroll
            for (int mt = 0; mt < 2; mt++)
                #pragma unroll
                for (int nt = 0; nt < 8; nt++)
                    mma_bf16(acc[mt][nt][0], acc[mt][nt][1], acc[mt][nt][2], acc[mt][nt][3],
                             a[mt][0], a[mt][1], a[mt][2], a[mt][3],
                             b[nt][0], b[nt][1]);
        }

        {
            const int g = lane >> 2, tq = lane & 3;
            #pragma unroll
            for (int mt = 0; mt < 2; mt++) {
                const int rowb = mrow * 32 + mt * 16 + g;
                #pragma unroll
                for (int gi = 0; gi < 4; gi++) {
                    float m0 = CUDART_INF_F, m1 = CUDART_INF_F;
                    #pragma unroll
                    for (int e = 0; e < 2; e++) {
                        const int nt = gi * 2 + e;
                        const int col = ncol * 64 + nt * 8 + tq * 2;
                        const float kq0 = ksq[col], kq1 = ksq[col + 1];
                        m0 = fminf(m0, fminf(fmaf(-2.f, acc[mt][nt][0], kq0),
                                             fmaf(-2.f, acc[mt][nt][1], kq1)));
                        m1 = fminf(m1, fminf(fmaf(-2.f, acc[mt][nt][2], kq0),
                                             fmaf(-2.f, acc[mt][nt][3], kq1)));
                    }
                    m0 = fminf(m0, __shfl_xor_sync(0xFFFFFFFFu, m0, 1));
                    m0 = fminf(m0, __shfl_xor_sync(0xFFFFFFFFu, m0, 2));
                    m1 = fminf(m1, __shfl_xor_sync(0xFFFFFFFFu, m1, 1));
                    m1 = fminf(m1, __shfl_xor_sync(0xFFFFFFFFu, m1, 2));
                    if (tq == 0) {
                        const int gg = ncol * 4 + gi;
                        stage[rowb * 8 + gg]       = m0;
                        stage[(rowb + 8) * 8 + gg] = m1;
                    }
                }
            }
        }
        __syncthreads();

        {
            const int row = tid >> 1, half = tid & 1;
            float4 v = *(float4*)&stage[row * 8 + half * 4];
            *(float4*)&g_hmin[(size_t)row * NHG + t * 8 + half * 4] = v;
        }

        if (have_next) {
            asm volatile("cp.async.wait_group 0;" ::: "memory");
            __syncthreads();
            const int row = tid >> 2, qtr = tid & 3;
            const int j = (t + GRID1) * KT + row;
            const float4* s = (const float4*)(smem + SM_ST32 + row * 256 + qtr * 64);
            char* dst = smem + (p ? SM_K0 : SM_K1) + row * TSTRIDE_B + qtr * 32;
            float ss = 0.f;
            uint2* d = (uint2*)dst;
            #pragma unroll
            for (int i = 0; i < 4; i++) {
                float4 v = s[i];
                ss = fmaf(v.x, v.x, ss); ss = fmaf(v.y, v.y, ss);
                ss = fmaf(v.z, v.z, ss); ss = fmaf(v.w, v.w, ss);
                __nv_bfloat162 p0 = __floats2bfloat162_rn(v.x, v.y);
                __nv_bfloat162 p1 = __floats2bfloat162_rn(v.z, v.w);
                uint2 u;
                u.x = *(uint32_t*)&p0;
                u.y = *(uint32_t*)&p1;
                d[i] = u;
            }
            ss += __shfl_xor_sync(0xFFFFFFFFu, ss, 1);
            ss += __shfl_xor_sync(0xFFFFFFFFu, ss, 2);
            if (qtr == 0)
                ((float*)(smem + (p ? SM_KSQ0 : SM_KSQ1)))[row] =
                    (j < NK) ? ss : CUDART_INF_F;
        }
        __syncthreads();
        p ^= 1;
    }
}

// ======================================================================
// Kernel 2: cutoff -> compact -> exact fp32 rescore -> exact top-8,
// with register/shuffle bitonic top-8 merges (no smem trees).
// grid NQ, 256 threads.
// ======================================================================
#define INS1(s_)                                                                 \
    if ((s_) < l[7]) {                                                           \
        l[7] = (s_);                                                             \
        _Pragma("unroll")                                                        \
        for (int u = 7; u > 0; u--)                                              \
            if (l[u] < l[u-1]) { float ts = l[u]; l[u] = l[u-1]; l[u-1] = ts; }  \
    }

// merge own sorted-asc 8-list with shfl_xor partner's, keep 8 smallest sorted
__device__ __forceinline__ void wmerge8_f(float l[8], int off) {
    float b[8];
    #pragma unroll
    for (int i = 0; i < 8; i++) b[i] = __shfl_xor_sync(0xFFFFFFFFu, l[i], off);
    float t[8];
    #pragma unroll
    for (int i = 0; i < 8; i++) t[i] = fminf(l[i], b[7 - i]);   // bitonic
    #pragma unroll
    for (int d = 4; d >= 1; d >>= 1)
        #pragma unroll
        for (int i = 0; i < 8; i++)
            if ((i & d) == 0) {
                float mn = fminf(t[i], t[i + d]);
                float mx = fmaxf(t[i], t[i + d]);
                t[i] = mn; t[i + d] = mx;
            }
    #pragma unroll
    for (int i = 0; i < 8; i++) l[i] = t[i];
}

__device__ __forceinline__ void wmerge8_u64(unsigned long long l[8], int off) {
    unsigned long long b[8];
    #pragma unroll
    for (int i = 0; i < 8; i++) b[i] = __shfl_xor_sync(0xFFFFFFFFu, l[i], off);
    unsigned long long t[8];
    #pragma unroll
    for (int i = 0; i < 8; i++) t[i] = (l[i] < b[7 - i]) ? l[i] : b[7 - i];
    #pragma unroll
    for (int d = 4; d >= 1; d >>= 1)
        #pragma unroll
        for (int i = 0; i < 8; i++)
            if ((i & d) == 0) {
                unsigned long long mn = (t[i] < t[i + d]) ? t[i] : t[i + d];
                unsigned long long mx = (t[i] < t[i + d]) ? t[i + d] : t[i];
                t[i] = mn; t[i + d] = mx;
            }
    #pragma unroll
    for (int i = 0; i < 8; i++) l[i] = t[i];
}

// monotone float->uint map (order-preserving for all finite floats)
__device__ __forceinline__ uint32_t fmono(float s) {
    uint32_t b = __float_as_uint(s);
    uint32_t mask = (uint32_t)(-(int32_t)(b >> 31)) | 0x80000000u;
    return b ^ mask;
}

__global__ __launch_bounds__(256) void knn_select(
    const float* __restrict__ qm, const float* __restrict__ km)
{
    __shared__ float qs[64];
    __shared__ float ws[8 * 8];               // warp top-8 lists (phase A)
    __shared__ unsigned long long wq[8 * 8];  // warp top-8 key lists (phase C)
    __shared__ int   s_list[CAP];
    __shared__ int   s_cnt;
    __shared__ float s_cut;
    const int q = blockIdx.x, tid = threadIdx.x;
    const int wid = tid >> 5, lane = tid & 31;

    if (tid < 64) qs[tid] = qm[(size_t)q * DD + tid];
    if (tid == 0) s_cnt = 0;

    const float4* h4 = (const float4*)&g_hmin[(size_t)q * NHG];
    const int NV = NHG / 4;   // 782 float4

    // ---- phase A: per-thread top-8 scan, then shuffle-bitonic reduce ----
    float l[8];
    #pragma unroll
    for (int i = 0; i < 8; i++) l[i] = CUDART_INF_F;
    #pragma unroll
    for (int r = 0; r < 4; r++) {
        const int v4 = tid + r * 256;
        if (v4 < NV) {
            float4 v = h4[v4];
            INS1(v.x); INS1(v.y); INS1(v.z); INS1(v.w);
        }
    }
    wmerge8_f(l, 16); wmerge8_f(l, 8); wmerge8_f(l, 4);
    wmerge8_f(l, 2);  wmerge8_f(l, 1);
    if (lane == 0) {
        #pragma unroll
        for (int i = 0; i < 8; i++) ws[wid * 8 + i] = l[i];
    }
    __syncthreads();
    if (wid == 0) {
        float m[8];
        #pragma unroll
        for (int i = 0; i < 8; i++)
            m[i] = (lane < 8) ? ws[lane * 8 + i] : CUDART_INF_F;
        wmerge8_f(m, 4); wmerge8_f(m, 2); wmerge8_f(m, 1);
        if (lane == 0) s_cut = m[7] + MARGIN;
    }
    __syncthreads();

    // ---- phase B: compact candidate 16-key groups ----
    const float cut = s_cut;
    #pragma unroll
    for (int r = 0; r < 4; r++) {
        const int v4 = tid + r * 256;
        if (v4 < NV) {
            float4 v = h4[v4];
            if (v.x <= cut) { int p = atomicAdd(&s_cnt, 1); if (p < CAP) s_list[p] = v4 * 4; }
            if (v.y <= cut) { int p = atomicAdd(&s_cnt, 1); if (p < CAP) s_list[p] = v4 * 4 + 1; }
            if (v.z <= cut) { int p = atomicAdd(&s_cnt, 1); if (p < CAP) s_list[p] = v4 * 4 + 2; }
            if (v.w <= cut) { int p = atomicAdd(&s_cnt, 1); if (p < CAP) s_list[p] = v4 * 4 + 3; }
        }
    }
    __syncthreads();
    const int cnt = (s_cnt < CAP) ? s_cnt : CAP;

    // ---- phase C: exact fp32 rescore, u64 (mono(s),idx) keys ----
    unsigned long long kk[8];
    #pragma unroll
    for (int i = 0; i < 8; i++) kk[i] = 0xFFFFFFFFFFFFFFFFull;

    const float4* qp = (const float4*)qs;
    for (int u = tid; u < cnt * GRP; u += 256) {
        const int j = s_list[u >> 4] * GRP + (u & 15);
        if (j < NK) {
            const float4* kp = (const float4*)(km + (size_t)j * DD);
            float dot = 0.f, ks = 0.f;
            #pragma unroll
            for (int w = 0; w < 16; w++) {
                float4 kv = kp[w];
                float4 qv = qp[w];
                dot = fmaf(kv.x, qv.x, dot); ks = fmaf(kv.x, kv.x, ks);
                dot = fmaf(kv.y, qv.y, dot); ks = fmaf(kv.y, kv.y, ks);
                dot = fmaf(kv.z, qv.z, dot); ks = fmaf(kv.z, kv.z, ks);
                dot = fmaf(kv.w, qv.w, dot); ks = fmaf(kv.w, kv.w, ks);
            }
            float s = fmaf(-2.f, dot, ks);
            unsigned long long key = ((unsigned long long)fmono(s) << 32) | (uint32_t)j;
            if (key < kk[7]) {
                kk[7] = key;
                #pragma unroll
                for (int v = 7; v > 0; v--)
                    if (kk[v] < kk[v-1]) {
                        unsigned long long tv = kk[v]; kk[v] = kk[v-1]; kk[v-1] = tv;
                    }
            }
        }
    }
    wmerge8_u64(kk, 16); wmerge8_u64(kk, 8); wmerge8_u64(kk, 4);
    wmerge8_u64(kk, 2);  wmerge8_u64(kk, 1);
    if (lane == 0) {
        #pragma unroll
        for (int i = 0; i < 8; i++) wq[wid * 8 + i] = kk[i];
    }
    __syncthreads();
    if (wid == 0) {
        unsigned long long m[8];
        #pragma unroll
        for (int i = 0; i < 8; i++)
            m[i] = (lane < 8) ? wq[lane * 8 + i] : 0xFFFFFFFFFFFFFFFFull;
        wmerge8_u64(m, 4); wmerge8_u64(m, 2); wmerge8_u64(m, 1);
        if (lane == 0) {
            #pragma unroll
            for (int i = 0; i < 8; i++)
                g_topidx[q * 8 + i] = (int)(uint32_t)(m[i] & 0xFFFFFFFFull);
        }
    }
}

// ======================================================================
// Kernel 3: gather obs[idx] -> out [8, 256, 3072]  (2048 blocks, max MLP)
// ======================================================================
__global__ __launch_bounds__(256) void knn_gather_kernel(
    const float* __restrict__ obs, float* __restrict__ out)
{
    const int b  = blockIdx.x;
    const int kk = b >> 8;
    const int q  = b & 255;
    const int src = g_topidx[q * 8 + kk];

    const float4* s = (const float4*)(obs + (size_t)src * OBS_ELEMS);
    float4*       d = (float4*)(out + ((size_t)kk * NQ + q) * OBS_ELEMS);

    #pragma unroll
    for (int i = threadIdx.x; i < OBS_ELEMS / 4; i += 256)
        d[i] = s[i];
}

// ======================================================================
extern "C" void kernel_launch(void* const* d_in, const int* in_sizes, int n_in,
                              void* d_out, int out_size)
{
    const float* q   = (const float*)d_in[0];
    const float* k   = (const float*)d_in[1];
    const float* obs = (const float*)d_in[2];
    float* out = (float*)d_out;

    cudaFuncSetAttribute(knn_score_min,
                         cudaFuncAttributeMaxDynamicSharedMemorySize, SM_TOTAL);

    knn_score_min<<<GRID1, 512, SM_TOTAL>>>(q, k);
    knn_select<<<NQ, 256>>>(q, k);
    knn_gather_kernel<<<NQ * 8, 256>>>(obs, out);
}